// round 15
// baseline (speedup 1.0000x reference)
#include <cuda_runtime.h>
#include <cuda_fp16.h>
#include <cstdint>
#include <math.h>

#define KB 2
#define KS 2048
#define KD 1024
#define KH 16
#define KHD 64
#define KBH (KB * KH)
#define KM (KB * KS)
#define MW (KS / 32)
#define LOG2E 1.4426950408889634f

// fp16 copies + intermediates (device globals: allocation-free)
__device__ __half g_xq[KB * KS * KD];
__device__ __half g_xk[KB * KS * KD];
__device__ __half g_xv[KB * KS * KD];
__device__ __half g_wq[KD * KD];
__device__ __half g_wout[KD * KD];
__device__ uint32_t g_mbits[KB * KS * MW];
__device__ int g_allones;
__device__ __half g_qp[KBH * KS * KHD];
__device__ __half g_kp[KBH * KS * KHD];
__device__ __half g_vp[KBH * KS * KHD];
__device__ __half g_ctx[KB * KS * KD];
__device__ float g_lg2[KBH * KS];      // per-row -log2(sum exp)

// ---------------------------------------------------------------------------
__device__ __forceinline__ uint32_t packh2(float a, float b) {
    __half2 h = __floats2half2_rn(a, b);
    return *reinterpret_cast<uint32_t*>(&h);
}
__device__ __forceinline__ float ex2(float x) {
    float y;
    asm("ex2.approx.ftz.f32 %0, %1;" : "=f"(y) : "f"(x));
    return y;
}
__device__ __forceinline__ void mma16(float* c, const uint32_t* a, const uint32_t* b) {
    asm volatile(
        "mma.sync.aligned.m16n8k16.row.col.f32.f16.f16.f32 "
        "{%0,%1,%2,%3}, {%4,%5,%6,%7}, {%8,%9}, {%0,%1,%2,%3};\n"
        : "+f"(c[0]), "+f"(c[1]), "+f"(c[2]), "+f"(c[3])
        : "r"(a[0]), "r"(a[1]), "r"(a[2]), "r"(a[3]), "r"(b[0]), "r"(b[1]));
}
__device__ __forceinline__ void ldm_x4(uint32_t* r, const void* p) {
    uint32_t a = (uint32_t)__cvta_generic_to_shared(p);
    asm volatile("ldmatrix.sync.aligned.m8n8.x4.shared.b16 {%0,%1,%2,%3}, [%4];"
                 : "=r"(r[0]), "=r"(r[1]), "=r"(r[2]), "=r"(r[3]) : "r"(a));
}
__device__ __forceinline__ void ldm_x4_t(uint32_t* r, const void* p) {
    uint32_t a = (uint32_t)__cvta_generic_to_shared(p);
    asm volatile("ldmatrix.sync.aligned.m8n8.x4.trans.shared.b16 {%0,%1,%2,%3}, [%4];"
                 : "=r"(r[0]), "=r"(r[1]), "=r"(r[2]), "=r"(r[3]) : "r"(a));
}
__device__ __forceinline__ void cp16(void* s, const void* g) {
    uint32_t sa = (uint32_t)__cvta_generic_to_shared(s);
    asm volatile("cp.async.cg.shared.global [%0], [%1], 16;\n" :: "r"(sa), "l"(g));
}
__device__ __forceinline__ void cp_commit() { asm volatile("cp.async.commit_group;\n"); }
template<int N>
__device__ __forceinline__ void cp_wait() { asm volatile("cp.async.wait_group %0;\n" :: "n"(N)); }
__device__ __forceinline__ void stcs4(float* p, float x, float y, float z, float w) {
    asm volatile("st.global.cs.v4.f32 [%0], {%1,%2,%3,%4};"
                 :: "l"(p), "f"(x), "f"(y), "f"(z), "f"(w) : "memory");
}

// ---------------------------------------------------------------------------
// prep kernels
// ---------------------------------------------------------------------------
__global__ void __launch_bounds__(256) prep_half(const float* __restrict__ q,
                                                 const float* __restrict__ k,
                                                 const float* __restrict__ v,
                                                 const float* __restrict__ Wq,
                                                 const float* __restrict__ Wout) {
    if (blockIdx.x == 0 && threadIdx.x == 0) g_allones = 1;  // runs before prep_mask
    const int i = blockIdx.x * 256 + threadIdx.x;
    const float* src;
    __half* dst;
    size_t off;
    if (i < 3 * 1048576) {
        const int seg = i >> 20;
        off = (size_t)(i & 1048575) * 4;
        src = (seg == 0) ? q : (seg == 1) ? k : v;
        dst = (seg == 0) ? g_xq : (seg == 1) ? g_xk : g_xv;
    } else {
        const int j = i - 3 * 1048576;
        if (j < 262144) { src = Wq; dst = g_wq; off = (size_t)j * 4; }
        else { src = Wout; dst = g_wout; off = (size_t)(j - 262144) * 4; }
    }
    float4 f = *(const float4*)(src + off);
    __half2 h0 = __floats2half2_rn(f.x, f.y);
    __half2 h1 = __floats2half2_rn(f.z, f.w);
    *(uint2*)(dst + off) = make_uint2(*(uint32_t*)&h0, *(uint32_t*)&h1);
}

__global__ void __launch_bounds__(256) prep_mask(const int* __restrict__ mask) {
    const int w = blockIdx.x * 256 + threadIdx.x;
    const int* p = mask + (size_t)w * 32;
    uint32_t bits = 0;
#pragma unroll
    for (int j = 0; j < 8; j++) {
        int4 m = *(const int4*)(p + j * 4);
        bits |= (uint32_t)(m.x != 0) << (4 * j)
              | (uint32_t)(m.y != 0) << (4 * j + 1)
              | (uint32_t)(m.z != 0) << (4 * j + 2)
              | (uint32_t)(m.w != 0) << (4 * j + 3);
    }
    g_mbits[w] = bits;
    if (bits != 0xffffffffu) g_allones = 0;   // racy but all writers write 0
}

// ---------------------------------------------------------------------------
// GEMM-NT fp16, BK=64, XOR-swizzled 128B rows, 3-stage cp.async ring.
// Block tile 256x128, 8 warps in 4(M) x 2(N) grid, 64x64 warp tiles:
// per ks-step 8 LDSM.x4 feed 32 mma (33% fewer LDSM than 64x32 tiles).
// 1 CTA/SM. dynamic smem: 3*(256+128)*64*2 = 147,456 B
// ---------------------------------------------------------------------------
template<int MODE>
__global__ void __launch_bounds__(256, 1) gemm16(const float* __restrict__ bias,
                                                 float* __restrict__ Of) {
    extern __shared__ __half gsm[];
    __half (*As)[256][64] = (__half(*)[256][64])gsm;
    __half (*Bs)[128][64] = (__half(*)[128][64])(gsm + 3 * 256 * 64);

    const int z = (MODE == 0) ? blockIdx.z : 0;
    const __half* X = (MODE == 1) ? g_ctx : (z == 0 ? g_xq : (z == 1 ? g_xk : g_xv));
    const __half* W = (MODE == 1) ? g_wout : g_wq;
    __half* O16 = (z == 0) ? g_qp : (z == 1) ? g_kp : g_vp;

    const int tid = threadIdx.x;
    const int warp = tid >> 5, lane = tid & 31;
    const int g = lane >> 2, t = lane & 3;
    const int mat = lane >> 3, rr = lane & 7;
    const int wm = warp & 3, wn = warp >> 2;   // 4(M) x 2(N)
    const int m0 = wm * 64, n0 = wn * 64;
    const int mblk = blockIdx.y * 256, nblk = blockIdx.x * 128;

    float acc[4][8][4];
#pragma unroll
    for (int i = 0; i < 4; i++)
#pragma unroll
        for (int j = 0; j < 8; j++)
#pragma unroll
            for (int r = 0; r < 4; r++) acc[i][j][r] = 0.f;

    auto loadAB = [&](int kt, int buf) {
        const int k0 = kt * 64;
#pragma unroll
        for (int i = 0; i < 8; i++) {           // A: 256 rows x 8 chunks
            const int c = tid + i * 256;
            const int row = c >> 3;
            const int pch = c & 7;
            const int lch = pch ^ (row & 7);
            cp16(&As[buf][row][pch * 8], &X[(size_t)(mblk + row) * KD + k0 + lch * 8]);
        }
#pragma unroll
        for (int i = 0; i < 4; i++) {           // B: 128 rows x 8 chunks
            const int c = tid + i * 256;
            const int row = c >> 3;
            const int pch = c & 7;
            const int lch = pch ^ (row & 7);
            cp16(&Bs[buf][row][pch * 8], &W[(size_t)(nblk + row) * KD + k0 + lch * 8]);
        }
    };

    loadAB(0, 0); cp_commit();
    loadAB(1, 1); cp_commit();

    const int NT = KD / 64;   // 16
    for (int kt = 0; kt < NT; kt++) {
        if (kt + 2 < NT) cp_wait<1>(); else cp_wait<0>();
        __syncthreads();
        if (kt + 2 < NT) { loadAB(kt + 2, (kt + 2) % 3); cp_commit(); }
        const int buf = kt % 3;

#pragma unroll
        for (int ks = 0; ks < 4; ks++) {
            uint32_t af[4][4], bf[4][4];
#pragma unroll
            for (int mi = 0; mi < 4; mi++)
                ldm_x4(af[mi], &As[buf][m0 + mi * 16 + ((mat & 1) << 3) + rr]
                                       [(((ks << 1) + (mat >> 1)) ^ rr) * 8]);
#pragma unroll
            for (int p = 0; p < 4; p++)
                ldm_x4(bf[p], &Bs[buf][n0 + p * 16 + ((mat >> 1) << 3) + rr]
                                      [(((ks << 1) + (mat & 1)) ^ rr) * 8]);
#pragma unroll
            for (int mi = 0; mi < 4; mi++) {
#pragma unroll
                for (int p = 0; p < 4; p++) {
                    mma16(acc[mi][2 * p],     af[mi], &bf[p][0]);
                    mma16(acc[mi][2 * p + 1], af[mi], &bf[p][2]);
                }
            }
        }
    }

#pragma unroll
    for (int mi = 0; mi < 4; mi++) {
#pragma unroll
        for (int ni = 0; ni < 8; ni++) {
            const int gm = mblk + m0 + mi * 16 + g;
            const int gn = nblk + n0 + ni * 8 + 2 * t;
            const float b0 = __ldg(&bias[gn]), b1 = __ldg(&bias[gn + 1]);
            const float v00 = acc[mi][ni][0] + b0, v01 = acc[mi][ni][1] + b1;
            const float v10 = acc[mi][ni][2] + b0, v11 = acc[mi][ni][3] + b1;
            if (MODE == 1) {
                float* dst = &Of[(size_t)gm * KD + gn];
                *(float2*)dst = make_float2(v00, v01);
                *(float2*)(dst + (size_t)8 * KD) = make_float2(v10, v11);
            } else {
                const int b = gm >> 11, s = gm & (KS - 1);
                const int h = gn >> 6, hd = gn & 63;
                __half* dst = &O16[((size_t)(b * KH + h) * KS + s) * KHD + hd];
                *(uint32_t*)dst = packh2(v00, v01);
                *(uint32_t*)(dst + (size_t)8 * KHD) = packh2(v10, v11);
            }
        }
    }
}

// ---------------------------------------------------------------------------
// PASS 1: row sums of exp(s) -> g_lg2 = -log2(sum).  (R11 geometry, proven)
// 64 rows/block (grid 1024), warp (wr 0..1, wc 0..3) = 32r x 32c.
// K-only 3-stage ring: 49,152 B dynamic.
// ---------------------------------------------------------------------------
__global__ void __launch_bounds__(256, 2) fused_stats() {
    extern __shared__ __half sm1[];
    __half (*Ks)[128][64] = (__half(*)[128][64])sm1;
    __shared__ float sred[2][32][4];

    const int tid = threadIdx.x;
    const int w = tid >> 5, lane = tid & 31;
    const int wr = w >> 2, wc = w & 3;
    const int g = lane >> 2, t = lane & 3;
    const int mat = lane >> 3, rr = lane & 7;
    const int bh = blockIdx.y;
    const int b = bh >> 4;
    const int mblk = blockIdx.x * 64;
    const bool mall = (g_allones != 0);

    const __half* Qb = g_qp + (size_t)bh * KS * KHD;
    const __half* Kb = g_kp + (size_t)bh * KS * KHD;

    const int rbase = mblk + wr * 32;

    uint32_t aq[8][4];
    {
        const __half2 sc = __float2half2_rn(0.125f);
#pragma unroll
        for (int ks = 0; ks < 4; ks++) {
#pragma unroll
            for (int m = 0; m < 2; m++) {
                const __half* q0 = &Qb[(size_t)(rbase + m * 16 + g) * KHD + ks * 16 + 2 * t];
                const __half* q1 = q0 + 8 * KHD;
                __half2 h0 = __hmul2(*(const __half2*)q0, sc);
                __half2 h1 = __hmul2(*(const __half2*)q1, sc);
                __half2 h2 = __hmul2(*(const __half2*)(q0 + 8), sc);
                __half2 h3 = __hmul2(*(const __half2*)(q1 + 8), sc);
                aq[ks * 2 + m][0] = *reinterpret_cast<uint32_t*>(&h0);
                aq[ks * 2 + m][1] = *reinterpret_cast<uint32_t*>(&h1);
                aq[ks * 2 + m][2] = *reinterpret_cast<uint32_t*>(&h2);
                aq[ks * 2 + m][3] = *reinterpret_cast<uint32_t*>(&h3);
            }
        }
    }

    auto loadK = [&](int kt, int buf) {
#pragma unroll
        for (int i = 0; i < 4; i++) {
            const int c = tid + i * 256;
            const int row = c >> 3;
            const int pch = c & 7;
            const int lch = pch ^ (row & 7);
            cp16(&Ks[buf][row][pch * 8], &Kb[(size_t)(kt * 128 + row) * KHD + lch * 8]);
        }
    };

    const size_t mbase = ((size_t)b * KS + rbase + g) * MW + wc;
    float rs[2][2] = {{0.f, 0.f}, {0.f, 0.f}};

    loadK(0, 0); cp_commit();
    loadK(1, 1); cp_commit();
    for (int kt = 0; kt < 16; kt++) {
        if (kt < 14) cp_wait<1>(); else cp_wait<0>();
        __syncthreads();
        if (kt + 2 < 16) { loadK(kt + 2, (kt + 2) % 3); cp_commit(); }
        const int buf = kt % 3;

        float acc[2][4][4];
#pragma unroll
        for (int mI = 0; mI < 2; mI++)
#pragma unroll
            for (int n = 0; n < 4; n++)
#pragma unroll
                for (int r = 0; r < 4; r++) acc[mI][n][r] = 0.f;
#pragma unroll
        for (int ks = 0; ks < 4; ks++) {
#pragma unroll
            for (int nc = 0; nc < 2; nc++) {
                uint32_t bb[4];
                ldm_x4(bb, &Ks[buf][wc * 32 + nc * 16 + ((mat >> 1) << 3) + rr]
                                   [((ks * 2 + (mat & 1)) ^ rr) * 8]);
#pragma unroll
                for (int m = 0; m < 2; m++) {
                    mma16(acc[m][nc * 2],     aq[ks * 2 + m], bb);
                    mma16(acc[m][nc * 2 + 1], aq[ks * 2 + m], bb + 2);
                }
            }
        }

        if (mall) {
#pragma unroll
            for (int m = 0; m < 2; m++) {
                float a0 = 0.f, a1 = 0.f;
#pragma unroll
                for (int n = 0; n < 4; n++) {
                    a0 += ex2(acc[m][n][0] * LOG2E) + ex2(acc[m][n][1] * LOG2E);
                    a1 += ex2(acc[m][n][2] * LOG2E) + ex2(acc[m][n][3] * LOG2E);
                }
                rs[m][0] += a0; rs[m][1] += a1;
            }
        } else {
#pragma unroll
            for (int m = 0; m < 2; m++) {
                const uint32_t w0 = g_mbits[mbase + (size_t)(m * 16) * MW + kt * 4];
                const uint32_t w1 = g_mbits[mbase + (size_t)(m * 16 + 8) * MW + kt * 4];
#pragma unroll
                for (int n = 0; n < 4; n++) {
                    const int sh = n * 8 + 2 * t;
                    rs[m][0] += ((w0 >> sh) & 1) ? ex2(acc[m][n][0] * LOG2E) : 0.f;
                    rs[m][0] += ((w0 >> sh) & 2) ? ex2(acc[m][n][1] * LOG2E) : 0.f;
                    rs[m][1] += ((w1 >> sh) & 1) ? ex2(acc[m][n][2] * LOG2E) : 0.f;
                    rs[m][1] += ((w1 >> sh) & 2) ? ex2(acc[m][n][3] * LOG2E) : 0.f;
                }
            }
        }
    }

#pragma unroll
    for (int m = 0; m < 2; m++)
#pragma unroll
        for (int hf = 0; hf < 2; hf++) {
            rs[m][hf] += __shfl_xor_sync(0xffffffffu, rs[m][hf], 1);
            rs[m][hf] += __shfl_xor_sync(0xffffffffu, rs[m][hf], 2);
        }
    if (t == 0) {
#pragma unroll
        for (int m = 0; m < 2; m++)
#pragma unroll
            for (int hf = 0; hf < 2; hf++)
                sred[wr][m * 16 + hf * 8 + g][wc] = rs[m][hf];
    }
    __syncthreads();
    if (tid < 64) {
        const float* s4 = sred[tid >> 5][tid & 31];
        g_lg2[(size_t)bh * KS + mblk + tid] = -__log2f(s4[0] + s4[1] + s4[2] + s4[3]);
    }
}

// ---------------------------------------------------------------------------
// PASS 2 kernel: attn write + ctx. (one-barrier version, proven)
// ---------------------------------------------------------------------------
__global__ void __launch_bounds__(256, 2) fused_write(float* __restrict__ attn) {
    extern __shared__ __half sm2[];
    __half (*Ks)[128][64] = (__half(*)[128][64])sm2;
    __half (*Vs)[128][64] = (__half(*)[128][64])(sm2 + 3 * 128 * 64);
    __half* stage = sm2 + 5 * 128 * 64;   // 8 warps x 16 x 72 halves

    const int tid = threadIdx.x;
    const int w = tid >> 5, lane = tid & 31;
    const int wr = w >> 1, wc = w & 1;
    const int g = lane >> 2, t = lane & 3;
    const int mat = lane >> 3, rr = lane & 7;
    const int bh = blockIdx.y;
    const int b = bh >> 4, h = bh & 15;
    const int mblk = blockIdx.x * 64;
    const bool mall = (g_allones != 0);

    const __half* Qb = g_qp + (size_t)bh * KS * KHD;
    const __half* Kb = g_kp + (size_t)bh * KS * KHD;
    const __half* Vb = g_vp + (size_t)bh * KS * KHD;

    const int r0 = mblk + wr * 16 + g;
    const int r1 = r0 + 8;

    uint32_t aq[4][4];
    {
        const __half2 sc = __float2half2_rn(0.125f);
#pragma unroll
        for (int ks = 0; ks < 4; ks++) {
            const __half* q0 = &Qb[(size_t)r0 * KHD + ks * 16 + 2 * t];
            const __half* q1 = &Qb[(size_t)r1 * KHD + ks * 16 + 2 * t];
            __half2 h0 = __hmul2(*(const __half2*)q0, sc);
            __half2 h1 = __hmul2(*(const __half2*)q1, sc);
            __half2 h2 = __hmul2(*(const __half2*)(q0 + 8), sc);
            __half2 h3 = __hmul2(*(const __half2*)(q1 + 8), sc);
            aq[ks][0] = *reinterpret_cast<uint32_t*>(&h0);
            aq[ks][1] = *reinterpret_cast<uint32_t*>(&h1);
            aq[ks][2] = *reinterpret_cast<uint32_t*>(&h2);
            aq[ks][3] = *reinterpret_cast<uint32_t*>(&h3);
        }
    }

    const uint32_t* mb0 = g_mbits + ((size_t)b * KS + r0) * MW;
    const uint32_t* mb1 = mb0 + 8 * MW;

    const float lg2inv0 = g_lg2[(size_t)bh * KS + r0];
    const float lg2inv1 = g_lg2[(size_t)bh * KS + r1];

    auto loadK = [&](int kt, int buf) {
#pragma unroll
        for (int i = 0; i < 4; i++) {
            const int c = tid + i * 256;
            const int row = c >> 3;
            const int pch = c & 7;
            const int lch = pch ^ (row & 7);
            cp16(&Ks[buf][row][pch * 8], &Kb[(size_t)(kt * 128 + row) * KHD + lch * 8]);
        }
    };
    auto loadV = [&](int kt, int buf) {
#pragma unroll
        for (int i = 0; i < 4; i++) {
            const int c = tid + i * 256;
            const int row = c >> 3;
            const int pch = c & 7;
            const int lch = pch ^ (row & 7);
            cp16(&Vs[buf][row][pch * 8], &Vb[(size_t)(kt * 128 + row) * KHD + lch * 8]);
        }
    };

    float ctx[8][4];
#pragma unroll
    for (int ni = 0; ni < 8; ni++)
#pragma unroll
        for (int r = 0; r < 4; r++) ctx[ni][r] = 0.f;

    __half* swarp = stage + w * (16 * 72);
    const int sts0 = g * 72 + 2 * t;
    const int sts1 = (g + 8) * 72 + 2 * t;
    const int rb_half = (lane & 15) * 4;
    const int rb_row = lane >> 4;
    const size_t qrow_base = (size_t)bh * KS + mblk + wr * 16;

    loadK(0, 0); cp_commit();
    loadK(1, 1); cp_commit();
    loadV(0, 0); cp_commit();
    cp_wait<2>();
    __syncthreads();

    for (int kt = 0; kt < 16; kt++) {
        const int kbuf = kt % 3;
        const int vbuf = kt & 1;

        float acc[8][4];
#pragma unroll
        for (int ni = 0; ni < 8; ni++)
#pragma unroll
            for (int r = 0; r < 4; r++) acc[ni][r] = 0.f;

#pragma unroll
        for (int ks = 0; ks < 4; ks++) {
#pragma unroll
            for (int p = 0; p < 4; p++) {
                uint32_t bb[4];
                ldm_x4(bb, &Ks[kbuf][wc * 64 + p * 16 + ((mat >> 1) << 3) + rr]
                                    [((ks * 2 + (mat & 1)) ^ rr) * 8]);
                mma16(acc[2 * p],     aq[ks], bb);
                mma16(acc[2 * p + 1], aq[ks], bb + 2);
            }
        }

        uint32_t ap01[8], ap23[8];
        if (mall) {
#pragma unroll
            for (int ni = 0; ni < 8; ni++) {
                float p0 = ex2(fmaf(acc[ni][0], LOG2E, lg2inv0));
                float p1 = ex2(fmaf(acc[ni][1], LOG2E, lg2inv0));
                float p2 = ex2(fmaf(acc[ni][2], LOG2E, lg2inv1));
                float p3 = ex2(fmaf(acc[ni][3], LOG2E, lg2inv1));
                ap01[ni] = packh2(p0, p1);
                ap23[ni] = packh2(p2, p3);
            }
        } else {
            const uint2 mw0 = *(const uint2*)&mb0[kt * 4 + 2 * wc];
            const uint2 mw1 = *(const uint2*)&mb1[kt * 4 + 2 * wc];
#pragma unroll
            for (int ni = 0; ni < 8; ni++) {
                const uint32_t w0 = (ni < 4) ? mw0.x : mw0.y;
                const uint32_t w1 = (ni < 4) ? mw1.x : mw1.y;
                const int sh = (ni & 3) * 8 + 2 * t;
                float p0 = ((w0 >> sh) & 1) ? ex2(fmaf(acc[ni][0], LOG2E, lg2inv0)) : 0.f;
                float p1 = ((w0 >> sh) & 2) ? ex2(fmaf(acc[ni][1], LOG2E, lg2inv0)) : 0.f;
                float p2 = ((w1 >> sh) & 1) ? ex2(fmaf(acc[ni][2], LOG2E, lg2inv1)) : 0.f;
                float p3 = ((w1 >> sh) & 2) ? ex2(fmaf(acc[ni][3], LOG2E, lg2inv1)) : 0.f;
                ap01[ni] = packh2(p0, p1);
                ap23[ni] = packh2(p2, p3);
            }
        }
#pragma unroll
        for (int ni = 0; ni < 8; ni++) {
            *(uint32_t*)&swarp[sts0 + 8 * ni] = ap01[ni];
            *(uint32_t*)&swarp[sts1 + 8 * ni] = ap23[ni];
        }
        __syncwarp();
        {
            const int cbase = kt * 128 + wc * 64 + rb_half;
#pragma unroll
            for (int j = 0; j < 8; j++) {
                const int sr = 2 * j + rb_row;
                uint2 hv = *(const uint2*)&swarp[sr * 72 + rb_half];
                __half2 ha = *reinterpret_cast<__half2*>(&hv.x);
                __half2 hb = *reinterpret_cast<__half2*>(&hv.y);
                float2 fa = __half22float2(ha);
                float2 fb = __half22float2(hb);
                stcs4(&attn[(qrow_base + sr) * KS + cbase], fa.x, fa.y, fb.x, fb.y);
            }
        }
        __syncwarp();

        cp_wait<0>();
        __syncthreads();
        if (kt + 2 < 16) { loadK(kt + 2, (kt + 2) % 3); cp_commit(); }
        if (kt + 1 < 16) { loadV(kt + 1, (kt + 1) & 1); cp_commit(); }

#pragma unroll
        for (int j = 0; j < 4; j++) {
            uint32_t ap[4];
            ap[0] = ap01[2 * j];
            ap[1] = ap23[2 * j];
            ap[2] = ap01[2 * j + 1];
            ap[3] = ap23[2 * j + 1];
#pragma unroll
            for (int p = 0; p < 4; p++) {
                uint32_t bv[4];
                ldm_x4_t(bv, &Vs[vbuf][wc * 64 + j * 16 + ((mat & 1) << 3) + rr]
                                      [((p * 2 + (mat >> 1)) ^ rr) * 8]);
                mma16(ctx[2 * p],     ap, bv);
                mma16(ctx[2 * p + 1], ap, bv + 2);
            }
        }
    }

    __syncthreads();
    float* cbuf = (float*)sm2;                // [4][16][66]
    const int CST = 66;
    if (wc == 1) {
#pragma unroll
        for (int ni = 0; ni < 8; ni++) {
            const int c = ni * 8 + 2 * t;
            float* p0 = &cbuf[(wr * 16 + g) * CST + c];
            float* p1 = &cbuf[(wr * 16 + g + 8) * CST + c];
            p0[0] = ctx[ni][0]; p0[1] = ctx[ni][1];
            p1[0] = ctx[ni][2]; p1[1] = ctx[ni][3];
        }
    }
    __syncthreads();
    if (wc == 0) {
        __half* cb0 = &g_ctx[((size_t)(b * KS + r0)) * KD + h * KHD];
#pragma unroll
        for (int ni = 0; ni < 8; ni++) {
            const int c = ni * 8 + 2 * t;
            const float* p0 = &cbuf[(wr * 16 + g) * CST + c];
            const float* p1 = &cbuf[(wr * 16 + g + 8) * CST + c];
            *(uint32_t*)&cb0[c] = packh2(ctx[ni][0] + p0[0], ctx[ni][1] + p0[1]);
            *(uint32_t*)&cb0[(size_t)8 * KD + c] = packh2(ctx[ni][2] + p1[0], ctx[ni][3] + p1[1]);
        }
    }
}

// ---------------------------------------------------------------------------
extern "C" void kernel_launch(void* const* d_in, const int* in_sizes, int n_in,
                              void* d_out, int out_size) {
    const float* q    = (const float*)d_in[0];
    const float* k    = (const float*)d_in[1];
    const float* v    = (const float*)d_in[2];
    const int*   mask = (const int*)d_in[3];
    const float* Wq   = (const float*)d_in[4];
    const float* bq   = (const float*)d_in[5];
    const float* Wout = (const float*)d_in[6];
    const float* bout = (const float*)d_in[7];

    float* out  = (float*)d_out;
    float* attn = out + (size_t)KB * KS * KD;

    const int GEMM_SMEM  = 3 * (256 + 128) * 64 * (int)sizeof(__half); // 147,456 B
    const int STATS_SMEM = 3 * 128 * 64 * (int)sizeof(__half);         // 49,152 B
    const int WRITE_SMEM = (5 * 128 * 64 + 8 * 16 * 72) * (int)sizeof(__half); // 100,352 B
    cudaFuncSetAttribute(gemm16<0>, cudaFuncAttributeMaxDynamicSharedMemorySize, GEMM_SMEM);
    cudaFuncSetAttribute(gemm16<1>, cudaFuncAttributeMaxDynamicSharedMemorySize, GEMM_SMEM);
    cudaFuncSetAttribute(fused_stats, cudaFuncAttributeMaxDynamicSharedMemorySize, STATS_SMEM);
    cudaFuncSetAttribute(fused_write, cudaFuncAttributeMaxDynamicSharedMemorySize, WRITE_SMEM);

    prep_half<<<14336, 256>>>(q, k, v, Wq, Wout);
    prep_mask<<<1024, 256>>>(mask);

    dim3 gp(KD / 128, KM / 256, 3);   // (8, 16, 3) = 384 blocks
    gemm16<0><<<gp, 256, GEMM_SMEM>>>(bq, nullptr);

    dim3 ga(KS / 64, KBH);    // (32, 32) = 1024 blocks
    fused_stats<<<ga, 256, STATS_SMEM>>>();
    fused_write<<<ga, 256, WRITE_SMEM>>>(attn);

    dim3 go(KD / 128, KM / 256, 1);   // (8, 16) = 128 blocks
    gemm16<1><<<go, 256, GEMM_SMEM>>>(bout, out);
}

// round 16
// speedup vs baseline: 1.0244x; 1.0244x over previous
#include <cuda_runtime.h>
#include <cuda_fp16.h>
#include <cstdint>
#include <math.h>

#define KB 2
#define KS 2048
#define KD 1024
#define KH 16
#define KHD 64
#define KBH (KB * KH)
#define KM (KB * KS)
#define MW (KS / 32)
#define LOG2E 1.4426950408889634f

// fp16 copies + intermediates (device globals: allocation-free)
__device__ __half g_xq[KB * KS * KD];
__device__ __half g_xk[KB * KS * KD];
__device__ __half g_xv[KB * KS * KD];
__device__ __half g_wq[KD * KD];
__device__ __half g_wout[KD * KD];
__device__ uint32_t g_mbits[KB * KS * MW];
__device__ int g_allones;
__device__ __half g_qp[KBH * KS * KHD];
__device__ __half g_kp[KBH * KS * KHD];
__device__ __half g_vp[KBH * KS * KHD];
__device__ __half g_ctx[KB * KS * KD];
__device__ float g_lg2[KBH * KS];      // per-row -log2(sum exp)

// ---------------------------------------------------------------------------
__device__ __forceinline__ uint32_t packh2(float a, float b) {
    __half2 h = __floats2half2_rn(a, b);
    return *reinterpret_cast<uint32_t*>(&h);
}
__device__ __forceinline__ float ex2(float x) {
    float y;
    asm("ex2.approx.ftz.f32 %0, %1;" : "=f"(y) : "f"(x));
    return y;
}
__device__ __forceinline__ void mma16(float* c, const uint32_t* a, const uint32_t* b) {
    asm volatile(
        "mma.sync.aligned.m16n8k16.row.col.f32.f16.f16.f32 "
        "{%0,%1,%2,%3}, {%4,%5,%6,%7}, {%8,%9}, {%0,%1,%2,%3};\n"
        : "+f"(c[0]), "+f"(c[1]), "+f"(c[2]), "+f"(c[3])
        : "r"(a[0]), "r"(a[1]), "r"(a[2]), "r"(a[3]), "r"(b[0]), "r"(b[1]));
}
__device__ __forceinline__ void ldm_x4(uint32_t* r, const void* p) {
    uint32_t a = (uint32_t)__cvta_generic_to_shared(p);
    asm volatile("ldmatrix.sync.aligned.m8n8.x4.shared.b16 {%0,%1,%2,%3}, [%4];"
                 : "=r"(r[0]), "=r"(r[1]), "=r"(r[2]), "=r"(r[3]) : "r"(a));
}
__device__ __forceinline__ void ldm_x4_t(uint32_t* r, const void* p) {
    uint32_t a = (uint32_t)__cvta_generic_to_shared(p);
    asm volatile("ldmatrix.sync.aligned.m8n8.x4.trans.shared.b16 {%0,%1,%2,%3}, [%4];"
                 : "=r"(r[0]), "=r"(r[1]), "=r"(r[2]), "=r"(r[3]) : "r"(a));
}
__device__ __forceinline__ void cp16(void* s, const void* g) {
    uint32_t sa = (uint32_t)__cvta_generic_to_shared(s);
    asm volatile("cp.async.cg.shared.global [%0], [%1], 16;\n" :: "r"(sa), "l"(g));
}
__device__ __forceinline__ void cp_commit() { asm volatile("cp.async.commit_group;\n"); }
template<int N>
__device__ __forceinline__ void cp_wait() { asm volatile("cp.async.wait_group %0;\n" :: "n"(N)); }
__device__ __forceinline__ void stcs4(float* p, float x, float y, float z, float w) {
    asm volatile("st.global.cs.v4.f32 [%0], {%1,%2,%3,%4};"
                 :: "l"(p), "f"(x), "f"(y), "f"(z), "f"(w) : "memory");
}

// ---------------------------------------------------------------------------
// prep: MERGED fp32->fp16 conversion + mask bit-packing (one launch)
// blocks [0, 14336): convert q,k,v,Wq,Wout; blocks [14336, 15360): pack mask
// ---------------------------------------------------------------------------
__global__ void __launch_bounds__(256) prep_all(const float* __restrict__ q,
                                                const float* __restrict__ k,
                                                const float* __restrict__ v,
                                                const float* __restrict__ Wq,
                                                const float* __restrict__ Wout,
                                                const int* __restrict__ mask) {
    if (blockIdx.x == 0 && threadIdx.x == 0) g_allones = 1;
    if (blockIdx.x < 14336) {
        const int i = blockIdx.x * 256 + threadIdx.x;
        const float* src;
        __half* dst;
        size_t off;
        if (i < 3 * 1048576) {
            const int seg = i >> 20;
            off = (size_t)(i & 1048575) * 4;
            src = (seg == 0) ? q : (seg == 1) ? k : v;
            dst = (seg == 0) ? g_xq : (seg == 1) ? g_xk : g_xv;
        } else {
            const int j = i - 3 * 1048576;
            if (j < 262144) { src = Wq; dst = g_wq; off = (size_t)j * 4; }
            else { src = Wout; dst = g_wout; off = (size_t)(j - 262144) * 4; }
        }
        float4 f = *(const float4*)(src + off);
        __half2 h0 = __floats2half2_rn(f.x, f.y);
        __half2 h1 = __floats2half2_rn(f.z, f.w);
        *(uint2*)(dst + off) = make_uint2(*(uint32_t*)&h0, *(uint32_t*)&h1);
    } else {
        const int w = (blockIdx.x - 14336) * 256 + threadIdx.x;   // 262,144 words
        const int* p = mask + (size_t)w * 32;
        uint32_t bits = 0;
#pragma unroll
        for (int j = 0; j < 8; j++) {
            int4 m = *(const int4*)(p + j * 4);
            bits |= (uint32_t)(m.x != 0) << (4 * j)
                  | (uint32_t)(m.y != 0) << (4 * j + 1)
                  | (uint32_t)(m.z != 0) << (4 * j + 2)
                  | (uint32_t)(m.w != 0) << (4 * j + 3);
        }
        g_mbits[w] = bits;
        if (bits != 0xffffffffu) g_allones = 0;   // racy but all writers write 0
    }
}

// ---------------------------------------------------------------------------
// GEMM-NT fp16, BK=64, XOR-swizzled 128B rows, 3-stage cp.async ring,
// 64x32 warp tiles (2Mx4N), 2 CTAs/SM. (R13-exact, best measured)
// dynamic smem: As[3][128][64] + Bs[3][128][64] = 98,304 B
// ---------------------------------------------------------------------------
template<int MODE>
__global__ void __launch_bounds__(256, 2) gemm16(const float* __restrict__ bias,
                                                 float* __restrict__ Of) {
    extern __shared__ __half gsm[];
    __half (*As)[128][64] = (__half(*)[128][64])gsm;
    __half (*Bs)[128][64] = (__half(*)[128][64])(gsm + 3 * 128 * 64);

    const int z = (MODE == 0) ? blockIdx.z : 0;
    const __half* X = (MODE == 1) ? g_ctx : (z == 0 ? g_xq : (z == 1 ? g_xk : g_xv));
    const __half* W = (MODE == 1) ? g_wout : g_wq;
    __half* O16 = (z == 0) ? g_qp : (z == 1) ? g_kp : g_vp;

    const int tid = threadIdx.x;
    const int warp = tid >> 5, lane = tid & 31;
    const int g = lane >> 2, t = lane & 3;
    const int mat = lane >> 3, rr = lane & 7;
    const int wm = warp & 1, wn = warp >> 1;
    const int m0 = wm * 64, n0 = wn * 32;
    const int mblk = blockIdx.y * 128, nblk = blockIdx.x * 128;

    float acc[4][4][4];
#pragma unroll
    for (int i = 0; i < 4; i++)
#pragma unroll
        for (int j = 0; j < 4; j++)
#pragma unroll
            for (int r = 0; r < 4; r++) acc[i][j][r] = 0.f;

    auto loadAB = [&](int kt, int buf) {
        const int k0 = kt * 64;
#pragma unroll
        for (int i = 0; i < 4; i++) {
            const int c = tid + i * 256;
            const int row = c >> 3;
            const int pch = c & 7;
            const int lch = pch ^ (row & 7);
            cp16(&As[buf][row][pch * 8], &X[(size_t)(mblk + row) * KD + k0 + lch * 8]);
            cp16(&Bs[buf][row][pch * 8], &W[(size_t)(nblk + row) * KD + k0 + lch * 8]);
        }
    };

    loadAB(0, 0); cp_commit();
    loadAB(1, 1); cp_commit();

    const int NT = KD / 64;   // 16
    for (int kt = 0; kt < NT; kt++) {
        if (kt + 2 < NT) cp_wait<1>(); else cp_wait<0>();
        __syncthreads();
        if (kt + 2 < NT) { loadAB(kt + 2, (kt + 2) % 3); cp_commit(); }
        const int buf = kt % 3;

#pragma unroll
        for (int ks = 0; ks < 4; ks++) {
            uint32_t af[4][4], bf[2][4];
#pragma unroll
            for (int mi = 0; mi < 4; mi++)
                ldm_x4(af[mi], &As[buf][m0 + mi * 16 + ((mat & 1) << 3) + rr]
                                       [(((ks << 1) + (mat >> 1)) ^ rr) * 8]);
#pragma unroll
            for (int p = 0; p < 2; p++)
                ldm_x4(bf[p], &Bs[buf][n0 + p * 16 + ((mat >> 1) << 3) + rr]
                                      [(((ks << 1) + (mat & 1)) ^ rr) * 8]);
#pragma unroll
            for (int mi = 0; mi < 4; mi++) {
                mma16(acc[mi][0], af[mi], &bf[0][0]);
                mma16(acc[mi][1], af[mi], &bf[0][2]);
                mma16(acc[mi][2], af[mi], &bf[1][0]);
                mma16(acc[mi][3], af[mi], &bf[1][2]);
            }
        }
    }

#pragma unroll
    for (int mi = 0; mi < 4; mi++) {
#pragma unroll
        for (int ni = 0; ni < 4; ni++) {
            const int gm = mblk + m0 + mi * 16 + g;
            const int gn = nblk + n0 + ni * 8 + 2 * t;
            const float b0 = __ldg(&bias[gn]), b1 = __ldg(&bias[gn + 1]);
            const float v00 = acc[mi][ni][0] + b0, v01 = acc[mi][ni][1] + b1;
            const float v10 = acc[mi][ni][2] + b0, v11 = acc[mi][ni][3] + b1;
            if (MODE == 1) {
                float* dst = &Of[(size_t)gm * KD + gn];
                *(float2*)dst = make_float2(v00, v01);
                *(float2*)(dst + (size_t)8 * KD) = make_float2(v10, v11);
            } else {
                const int b = gm >> 11, s = gm & (KS - 1);
                const int h = gn >> 6, hd = gn & 63;
                __half* dst = &O16[((size_t)(b * KH + h) * KS + s) * KHD + hd];
                *(uint32_t*)dst = packh2(v00, v01);
                *(uint32_t*)(dst + (size_t)8 * KHD) = packh2(v10, v11);
            }
        }
    }
}

// ---------------------------------------------------------------------------
// PASS 1: row sums of exp(s) -> g_lg2 = -log2(sum).  (R11/R13 geometry, proven)
// ---------------------------------------------------------------------------
__global__ void __launch_bounds__(256, 2) fused_stats() {
    extern __shared__ __half sm1[];
    __half (*Ks)[128][64] = (__half(*)[128][64])sm1;
    __shared__ float sred[2][32][4];

    const int tid = threadIdx.x;
    const int w = tid >> 5, lane = tid & 31;
    const int wr = w >> 2, wc = w & 3;
    const int g = lane >> 2, t = lane & 3;
    const int mat = lane >> 3, rr = lane & 7;
    const int bh = blockIdx.y;
    const int b = bh >> 4;
    const int mblk = blockIdx.x * 64;
    const bool mall = (g_allones != 0);

    const __half* Qb = g_qp + (size_t)bh * KS * KHD;
    const __half* Kb = g_kp + (size_t)bh * KS * KHD;

    const int rbase = mblk + wr * 32;

    uint32_t aq[8][4];
    {
        const __half2 sc = __float2half2_rn(0.125f);
#pragma unroll
        for (int ks = 0; ks < 4; ks++) {
#pragma unroll
            for (int m = 0; m < 2; m++) {
                const __half* q0 = &Qb[(size_t)(rbase + m * 16 + g) * KHD + ks * 16 + 2 * t];
                const __half* q1 = q0 + 8 * KHD;
                __half2 h0 = __hmul2(*(const __half2*)q0, sc);
                __half2 h1 = __hmul2(*(const __half2*)q1, sc);
                __half2 h2 = __hmul2(*(const __half2*)(q0 + 8), sc);
                __half2 h3 = __hmul2(*(const __half2*)(q1 + 8), sc);
                aq[ks * 2 + m][0] = *reinterpret_cast<uint32_t*>(&h0);
                aq[ks * 2 + m][1] = *reinterpret_cast<uint32_t*>(&h1);
                aq[ks * 2 + m][2] = *reinterpret_cast<uint32_t*>(&h2);
                aq[ks * 2 + m][3] = *reinterpret_cast<uint32_t*>(&h3);
            }
        }
    }

    auto loadK = [&](int kt, int buf) {
#pragma unroll
        for (int i = 0; i < 4; i++) {
            const int c = tid + i * 256;
            const int row = c >> 3;
            const int pch = c & 7;
            const int lch = pch ^ (row & 7);
            cp16(&Ks[buf][row][pch * 8], &Kb[(size_t)(kt * 128 + row) * KHD + lch * 8]);
        }
    };

    const size_t mbase = ((size_t)b * KS + rbase + g) * MW + wc;
    float rs[2][2] = {{0.f, 0.f}, {0.f, 0.f}};

    loadK(0, 0); cp_commit();
    loadK(1, 1); cp_commit();
    for (int kt = 0; kt < 16; kt++) {
        if (kt < 14) cp_wait<1>(); else cp_wait<0>();
        __syncthreads();
        if (kt + 2 < 16) { loadK(kt + 2, (kt + 2) % 3); cp_commit(); }
        const int buf = kt % 3;

        float acc[2][4][4];
#pragma unroll
        for (int mI = 0; mI < 2; mI++)
#pragma unroll
            for (int n = 0; n < 4; n++)
#pragma unroll
                for (int r = 0; r < 4; r++) acc[mI][n][r] = 0.f;
#pragma unroll
        for (int ks = 0; ks < 4; ks++) {
#pragma unroll
            for (int nc = 0; nc < 2; nc++) {
                uint32_t bb[4];
                ldm_x4(bb, &Ks[buf][wc * 32 + nc * 16 + ((mat >> 1) << 3) + rr]
                                   [((ks * 2 + (mat & 1)) ^ rr) * 8]);
#pragma unroll
                for (int m = 0; m < 2; m++) {
                    mma16(acc[m][nc * 2],     aq[ks * 2 + m], bb);
                    mma16(acc[m][nc * 2 + 1], aq[ks * 2 + m], bb + 2);
                }
            }
        }

        if (mall) {
#pragma unroll
            for (int m = 0; m < 2; m++) {
                float a0 = 0.f, a1 = 0.f;
#pragma unroll
                for (int n = 0; n < 4; n++) {
                    a0 += ex2(acc[m][n][0] * LOG2E) + ex2(acc[m][n][1] * LOG2E);
                    a1 += ex2(acc[m][n][2] * LOG2E) + ex2(acc[m][n][3] * LOG2E);
                }
                rs[m][0] += a0; rs[m][1] += a1;
            }
        } else {
#pragma unroll
            for (int m = 0; m < 2; m++) {
                const uint32_t w0 = g_mbits[mbase + (size_t)(m * 16) * MW + kt * 4];
                const uint32_t w1 = g_mbits[mbase + (size_t)(m * 16 + 8) * MW + kt * 4];
#pragma unroll
                for (int n = 0; n < 4; n++) {
                    const int sh = n * 8 + 2 * t;
                    rs[m][0] += ((w0 >> sh) & 1) ? ex2(acc[m][n][0] * LOG2E) : 0.f;
                    rs[m][0] += ((w0 >> sh) & 2) ? ex2(acc[m][n][1] * LOG2E) : 0.f;
                    rs[m][1] += ((w1 >> sh) & 1) ? ex2(acc[m][n][2] * LOG2E) : 0.f;
                    rs[m][1] += ((w1 >> sh) & 2) ? ex2(acc[m][n][3] * LOG2E) : 0.f;
                }
            }
        }
    }

#pragma unroll
    for (int m = 0; m < 2; m++)
#pragma unroll
        for (int hf = 0; hf < 2; hf++) {
            rs[m][hf] += __shfl_xor_sync(0xffffffffu, rs[m][hf], 1);
            rs[m][hf] += __shfl_xor_sync(0xffffffffu, rs[m][hf], 2);
        }
    if (t == 0) {
#pragma unroll
        for (int m = 0; m < 2; m++)
#pragma unroll
            for (int hf = 0; hf < 2; hf++)
                sred[wr][m * 16 + hf * 8 + g][wc] = rs[m][hf];
    }
    __syncthreads();
    if (tid < 64) {
        const float* s4 = sred[tid >> 5][tid & 31];
        g_lg2[(size_t)bh * KS + mblk + tid] = -__log2f(s4[0] + s4[1] + s4[2] + s4[3]);
    }
}

// ---------------------------------------------------------------------------
// PASS 2 kernel: attn write + ctx. (one-barrier version, proven)
// ---------------------------------------------------------------------------
__global__ void __launch_bounds__(256, 2) fused_write(float* __restrict__ attn) {
    extern __shared__ __half sm2[];
    __half (*Ks)[128][64] = (__half(*)[128][64])sm2;
    __half (*Vs)[128][64] = (__half(*)[128][64])(sm2 + 3 * 128 * 64);
    __half* stage = sm2 + 5 * 128 * 64;   // 8 warps x 16 x 72 halves

    const int tid = threadIdx.x;
    const int w = tid >> 5, lane = tid & 31;
    const int wr = w >> 1, wc = w & 1;
    const int g = lane >> 2, t = lane & 3;
    const int mat = lane >> 3, rr = lane & 7;
    const int bh = blockIdx.y;
    const int b = bh >> 4, h = bh & 15;
    const int mblk = blockIdx.x * 64;
    const bool mall = (g_allones != 0);

    const __half* Qb = g_qp + (size_t)bh * KS * KHD;
    const __half* Kb = g_kp + (size_t)bh * KS * KHD;
    const __half* Vb = g_vp + (size_t)bh * KS * KHD;

    const int r0 = mblk + wr * 16 + g;
    const int r1 = r0 + 8;

    uint32_t aq[4][4];
    {
        const __half2 sc = __float2half2_rn(0.125f);
#pragma unroll
        for (int ks = 0; ks < 4; ks++) {
            const __half* q0 = &Qb[(size_t)r0 * KHD + ks * 16 + 2 * t];
            const __half* q1 = &Qb[(size_t)r1 * KHD + ks * 16 + 2 * t];
            __half2 h0 = __hmul2(*(const __half2*)q0, sc);
            __half2 h1 = __hmul2(*(const __half2*)q1, sc);
            __half2 h2 = __hmul2(*(const __half2*)(q0 + 8), sc);
            __half2 h3 = __hmul2(*(const __half2*)(q1 + 8), sc);
            aq[ks][0] = *reinterpret_cast<uint32_t*>(&h0);
            aq[ks][1] = *reinterpret_cast<uint32_t*>(&h1);
            aq[ks][2] = *reinterpret_cast<uint32_t*>(&h2);
            aq[ks][3] = *reinterpret_cast<uint32_t*>(&h3);
        }
    }

    const uint32_t* mb0 = g_mbits + ((size_t)b * KS + r0) * MW;
    const uint32_t* mb1 = mb0 + 8 * MW;

    const float lg2inv0 = g_lg2[(size_t)bh * KS + r0];
    const float lg2inv1 = g_lg2[(size_t)bh * KS + r1];

    auto loadK = [&](int kt, int buf) {
#pragma unroll
        for (int i = 0; i < 4; i++) {
            const int c = tid + i * 256;
            const int row = c >> 3;
            const int pch = c & 7;
            const int lch = pch ^ (row & 7);
            cp16(&Ks[buf][row][pch * 8], &Kb[(size_t)(kt * 128 + row) * KHD + lch * 8]);
        }
    };
    auto loadV = [&](int kt, int buf) {
#pragma unroll
        for (int i = 0; i < 4; i++) {
            const int c = tid + i * 256;
            const int row = c >> 3;
            const int pch = c & 7;
            const int lch = pch ^ (row & 7);
            cp16(&Vs[buf][row][pch * 8], &Vb[(size_t)(kt * 128 + row) * KHD + lch * 8]);
        }
    };

    float ctx[8][4];
#pragma unroll
    for (int ni = 0; ni < 8; ni++)
#pragma unroll
        for (int r = 0; r < 4; r++) ctx[ni][r] = 0.f;

    __half* swarp = stage + w * (16 * 72);
    const int sts0 = g * 72 + 2 * t;
    const int sts1 = (g + 8) * 72 + 2 * t;
    const int rb_half = (lane & 15) * 4;
    const int rb_row = lane >> 4;
    const size_t qrow_base = (size_t)bh * KS + mblk + wr * 16;

    loadK(0, 0); cp_commit();
    loadK(1, 1); cp_commit();
    loadV(0, 0); cp_commit();
    cp_wait<2>();
    __syncthreads();

    for (int kt = 0; kt < 16; kt++) {
        const int kbuf = kt % 3;
        const int vbuf = kt & 1;

        float acc[8][4];
#pragma unroll
        for (int ni = 0; ni < 8; ni++)
#pragma unroll
            for (int r = 0; r < 4; r++) acc[ni][r] = 0.f;

#pragma unroll
        for (int ks = 0; ks < 4; ks++) {
#pragma unroll
            for (int p = 0; p < 4; p++) {
                uint32_t bb[4];
                ldm_x4(bb, &Ks[kbuf][wc * 64 + p * 16 + ((mat >> 1) << 3) + rr]
                                    [((ks * 2 + (mat & 1)) ^ rr) * 8]);
                mma16(acc[2 * p],     aq[ks], bb);
                mma16(acc[2 * p + 1], aq[ks], bb + 2);
            }
        }

        uint32_t ap01[8], ap23[8];
        if (mall) {
#pragma unroll
            for (int ni = 0; ni < 8; ni++) {
                float p0 = ex2(fmaf(acc[ni][0], LOG2E, lg2inv0));
                float p1 = ex2(fmaf(acc[ni][1], LOG2E, lg2inv0));
                float p2 = ex2(fmaf(acc[ni][2], LOG2E, lg2inv1));
                float p3 = ex2(fmaf(acc[ni][3], LOG2E, lg2inv1));
                ap01[ni] = packh2(p0, p1);
                ap23[ni] = packh2(p2, p3);
            }
        } else {
            const uint2 mw0 = *(const uint2*)&mb0[kt * 4 + 2 * wc];
            const uint2 mw1 = *(const uint2*)&mb1[kt * 4 + 2 * wc];
#pragma unroll
            for (int ni = 0; ni < 8; ni++) {
                const uint32_t w0 = (ni < 4) ? mw0.x : mw0.y;
                const uint32_t w1 = (ni < 4) ? mw1.x : mw1.y;
                const int sh = (ni & 3) * 8 + 2 * t;
                float p0 = ((w0 >> sh) & 1) ? ex2(fmaf(acc[ni][0], LOG2E, lg2inv0)) : 0.f;
                float p1 = ((w0 >> sh) & 2) ? ex2(fmaf(acc[ni][1], LOG2E, lg2inv0)) : 0.f;
                float p2 = ((w1 >> sh) & 1) ? ex2(fmaf(acc[ni][2], LOG2E, lg2inv1)) : 0.f;
                float p3 = ((w1 >> sh) & 2) ? ex2(fmaf(acc[ni][3], LOG2E, lg2inv1)) : 0.f;
                ap01[ni] = packh2(p0, p1);
                ap23[ni] = packh2(p2, p3);
            }
        }
#pragma unroll
        for (int ni = 0; ni < 8; ni++) {
            *(uint32_t*)&swarp[sts0 + 8 * ni] = ap01[ni];
            *(uint32_t*)&swarp[sts1 + 8 * ni] = ap23[ni];
        }
        __syncwarp();
        {
            const int cbase = kt * 128 + wc * 64 + rb_half;
#pragma unroll
            for (int j = 0; j < 8; j++) {
                const int sr = 2 * j + rb_row;
                uint2 hv = *(const uint2*)&swarp[sr * 72 + rb_half];
                __half2 ha = *reinterpret_cast<__half2*>(&hv.x);
                __half2 hb = *reinterpret_cast<__half2*>(&hv.y);
                float2 fa = __half22float2(ha);
                float2 fb = __half22float2(hb);
                stcs4(&attn[(qrow_base + sr) * KS + cbase], fa.x, fa.y, fb.x, fb.y);
            }
        }
        __syncwarp();

        cp_wait<0>();
        __syncthreads();
        if (kt + 2 < 16) { loadK(kt + 2, (kt + 2) % 3); cp_commit(); }
        if (kt + 1 < 16) { loadV(kt + 1, (kt + 1) & 1); cp_commit(); }

#pragma unroll
        for (int j = 0; j < 4; j++) {
            uint32_t ap[4];
            ap[0] = ap01[2 * j];
            ap[1] = ap23[2 * j];
            ap[2] = ap01[2 * j + 1];
            ap[3] = ap23[2 * j + 1];
#pragma unroll
            for (int p = 0; p < 4; p++) {
                uint32_t bv[4];
                ldm_x4_t(bv, &Vs[vbuf][wc * 64 + j * 16 + ((mat & 1) << 3) + rr]
                                      [((p * 2 + (mat >> 1)) ^ rr) * 8]);
                mma16(ctx[2 * p],     ap, bv);
                mma16(ctx[2 * p + 1], ap, bv + 2);
            }
        }
    }

    __syncthreads();
    float* cbuf = (float*)sm2;                // [4][16][66]
    const int CST = 66;
    if (wc == 1) {
#pragma unroll
        for (int ni = 0; ni < 8; ni++) {
            const int c = ni * 8 + 2 * t;
            float* p0 = &cbuf[(wr * 16 + g) * CST + c];
            float* p1 = &cbuf[(wr * 16 + g + 8) * CST + c];
            p0[0] = ctx[ni][0]; p0[1] = ctx[ni][1];
            p1[0] = ctx[ni][2]; p1[1] = ctx[ni][3];
        }
    }
    __syncthreads();
    if (wc == 0) {
        __half* cb0 = &g_ctx[((size_t)(b * KS + r0)) * KD + h * KHD];
#pragma unroll
        for (int ni = 0; ni < 8; ni++) {
            const int c = ni * 8 + 2 * t;
            const float* p0 = &cbuf[(wr * 16 + g) * CST + c];
            const float* p1 = &cbuf[(wr * 16 + g + 8) * CST + c];
            *(uint32_t*)&cb0[c] = packh2(ctx[ni][0] + p0[0], ctx[ni][1] + p0[1]);
            *(uint32_t*)&cb0[(size_t)8 * KD + c] = packh2(ctx[ni][2] + p1[0], ctx[ni][3] + p1[1]);
        }
    }
}

// ---------------------------------------------------------------------------
extern "C" void kernel_launch(void* const* d_in, const int* in_sizes, int n_in,
                              void* d_out, int out_size) {
    const float* q    = (const float*)d_in[0];
    const float* k    = (const float*)d_in[1];
    const float* v    = (const float*)d_in[2];
    const int*   mask = (const int*)d_in[3];
    const float* Wq   = (const float*)d_in[4];
    const float* bq   = (const float*)d_in[5];
    const float* Wout = (const float*)d_in[6];
    const float* bout = (const float*)d_in[7];

    float* out  = (float*)d_out;
    float* attn = out + (size_t)KB * KS * KD;

    const int GEMM_SMEM  = 3 * 2 * 128 * 64 * (int)sizeof(__half);  // 98,304 B
    const int STATS_SMEM = 3 * 128 * 64 * (int)sizeof(__half);      // 49,152 B
    const int WRITE_SMEM = (5 * 128 * 64 + 8 * 16 * 72) * (int)sizeof(__half); // 100,352 B
    cudaFuncSetAttribute(gemm16<0>, cudaFuncAttributeMaxDynamicSharedMemorySize, GEMM_SMEM);
    cudaFuncSetAttribute(gemm16<1>, cudaFuncAttributeMaxDynamicSharedMemorySize, GEMM_SMEM);
    cudaFuncSetAttribute(fused_stats, cudaFuncAttributeMaxDynamicSharedMemorySize, STATS_SMEM);
    cudaFuncSetAttribute(fused_write, cudaFuncAttributeMaxDynamicSharedMemorySize, WRITE_SMEM);

    prep_all<<<15360, 256>>>(q, k, v, Wq, Wout, mask);

    dim3 gp(KD / 128, KM / 128, 3);
    gemm16<0><<<gp, 256, GEMM_SMEM>>>(bq, nullptr);

    dim3 ga(KS / 64, KBH);    // (32, 32) = 1024 blocks
    fused_stats<<<ga, 256, STATS_SMEM>>>();
    fused_write<<<ga, 256, WRITE_SMEM>>>(attn);

    dim3 go(KD / 128, KM / 128, 1);
    gemm16<1><<<go, 256, GEMM_SMEM>>>(bout, out);
}